// round 6
// baseline (speedup 1.0000x reference)
#include <cuda_runtime.h>

// ---------------------------------------------------------------------------
// GCN_11682311045288: 2-layer GCN via per-launch CSR build + gather aggregation.
// Inputs: x [N,128] f32, edge_index [2,E] int32, W1[128,64], b1[64], W2[64,64], b2[64]
// Output: z [N,64] f32
// ---------------------------------------------------------------------------

#define MAXN 131072
#define MAXE 2097152
#define F 64
#define F4 (F / 4)

typedef unsigned long long u64;

// Scratch (module-load allocated; allowed).
__device__ float4 g_xw[(size_t)MAXN * F4];
__device__ float4 g_h [(size_t)MAXN * F4];
__device__ float  g_dinv[MAXN];
__device__ int    g_deg [MAXN];
__device__ int    g_rowptr[MAXN];   // after k_fill: row end
__device__ int    g_part[512];
__device__ int2   g_csr[MAXE];

__device__ __forceinline__ u64 pack2(float lo, float hi) {
    u64 r;
    asm("mov.b64 %0, {%1, %2};" : "=l"(r) : "r"(__float_as_uint(lo)), "r"(__float_as_uint(hi)));
    return r;
}
__device__ __forceinline__ void unpack2(u64 v, float& lo, float& hi) {
    unsigned a, b;
    asm("mov.b64 {%0, %1}, %2;" : "=r"(a), "=r"(b) : "l"(v));
    lo = __uint_as_float(a); hi = __uint_as_float(b);
}
__device__ __forceinline__ void fma2(u64& acc, u64 a, u64 b) {
    asm("fma.rn.f32x2 %0, %1, %2, %0;" : "+l"(acc) : "l"(a), "l"(b));
}

// ---------------------------------------------------------------------------
__global__ void k_init(int n) {
    int i = blockIdx.x * blockDim.x + threadIdx.x;
    if (i < n) g_deg[i] = 0;
}

__global__ void k_deg_count(const int* __restrict__ dst, int E) {
    int i = blockIdx.x * blockDim.x + threadIdx.x;
    int stride = gridDim.x * blockDim.x;
    int E4 = E >> 2;
    const int4* dst4 = (const int4*)dst;
    for (int j = i; j < E4; j += stride) {
        int4 d = dst4[j];
        atomicAdd(&g_deg[d.x], 1);
        atomicAdd(&g_deg[d.y], 1);
        atomicAdd(&g_deg[d.z], 1);
        atomicAdd(&g_deg[d.w], 1);
    }
    for (int j = (E4 << 2) + i; j < E; j += stride)
        atomicAdd(&g_deg[dst[j]], 1);
}

// --- 3-phase exclusive scan of g_deg -> g_rowptr ---------------------------
__global__ void k_scan_part(int n) {
    __shared__ int s[256];
    int t = threadIdx.x;
    int i = blockIdx.x * 256 + t;
    int v = (i < n) ? g_deg[i] : 0;
    s[t] = v;
    __syncthreads();
    #pragma unroll
    for (int off = 1; off < 256; off <<= 1) {
        int u = (t >= off) ? s[t - off] : 0;
        __syncthreads();
        s[t] += u;
        __syncthreads();
    }
    if (i < n) g_rowptr[i] = s[t] - v;
    if (t == 255) g_part[blockIdx.x] = s[255];
}

__global__ void k_scan_mid(int nb) {
    __shared__ int s[512];
    int t = threadIdx.x;
    int v = (t < nb) ? g_part[t] : 0;
    s[t] = v;
    __syncthreads();
    #pragma unroll
    for (int off = 1; off < 512; off <<= 1) {
        int u = (t >= off) ? s[t - off] : 0;
        __syncthreads();
        s[t] += u;
        __syncthreads();
    }
    if (t < nb) g_part[t] = s[t] - v;
}

__global__ void k_scan_apply(int n) {
    int i = blockIdx.x * 256 + threadIdx.x;
    if (i < n) {
        g_rowptr[i] += g_part[blockIdx.x];
        g_dinv[i] = rsqrtf((float)(g_deg[i] + 1));
    }
}

// Bumps g_rowptr[d]; after this kernel g_rowptr[i] = row end.
__global__ void k_fill(const int* __restrict__ src,
                       const int* __restrict__ dst, int E) {
    int i = blockIdx.x * blockDim.x + threadIdx.x;
    int stride = gridDim.x * blockDim.x;
    int E4 = E >> 2;
    const int4* src4 = (const int4*)src;
    const int4* dst4 = (const int4*)dst;
    for (int j = i; j < E4; j += stride) {
        int4 s = src4[j];
        int4 d = dst4[j];
        int p0 = atomicAdd(&g_rowptr[d.x], 1);
        g_csr[p0] = make_int2(s.x, __float_as_int(g_dinv[s.x] * g_dinv[d.x]));
        int p1 = atomicAdd(&g_rowptr[d.y], 1);
        g_csr[p1] = make_int2(s.y, __float_as_int(g_dinv[s.y] * g_dinv[d.y]));
        int p2 = atomicAdd(&g_rowptr[d.z], 1);
        g_csr[p2] = make_int2(s.z, __float_as_int(g_dinv[s.z] * g_dinv[d.z]));
        int p3 = atomicAdd(&g_rowptr[d.w], 1);
        g_csr[p3] = make_int2(s.w, __float_as_int(g_dinv[s.w] * g_dinv[d.w]));
    }
    for (int j = (E4 << 2) + i; j < E; j += stride) {
        int s = src[j], d = dst[j];
        int p = atomicAdd(&g_rowptr[d], 1);
        g_csr[p] = make_int2(s, __float_as_int(g_dinv[s] * g_dinv[d]));
    }
}

// ---------------------------------------------------------------------------
// Register-tiled GEMM with packed f32x2 FMAs: C[64x64]/block, 256 threads,
// 16 outputs/thread held as 8 packed u64 accumulators.
template<int K, bool RELU, bool READ_GH>
__global__ void k_gemm(const float* __restrict__ Xp,
                       const float* __restrict__ W,
                       int n)
{
    __shared__ float Ws[K * 64];
    __shared__ float xst[K * 68];

    const float* __restrict__ X = READ_GH ? (const float*)g_h : Xp;
    float* __restrict__ xw = (float*)g_xw;

    int tid = threadIdx.x;
    int f = tid & 63;
    int g = tid >> 6;
    int row0 = blockIdx.x * 64;

    {
        const float4* W4 = (const float4*)W;
        #pragma unroll
        for (int i = tid; i < K * 16; i += 256)
            ((float4*)Ws)[i] = W4[i];
    }
    {
        const int KQ = K / 4;
        #pragma unroll
        for (int i = tid; i < 64 * KQ; i += 256) {
            int r = i / KQ;
            int k4 = (i - r * KQ) * 4;
            int rr = row0 + r;
            float4 v = make_float4(0.f, 0.f, 0.f, 0.f);
            if (rr < n)
                v = ((const float4*)X)[((size_t)rr * K + k4) >> 2];
            if (RELU) {
                v.x = fmaxf(v.x, 0.f); v.y = fmaxf(v.y, 0.f);
                v.z = fmaxf(v.z, 0.f); v.w = fmaxf(v.w, 0.f);
            }
            xst[(k4 + 0) * 68 + r] = v.x;
            xst[(k4 + 1) * 68 + r] = v.y;
            xst[(k4 + 2) * 68 + r] = v.z;
            xst[(k4 + 3) * 68 + r] = v.w;
        }
    }
    __syncthreads();

    u64 accp[8];
    #pragma unroll
    for (int i = 0; i < 8; ++i) accp[i] = 0ull;
    const int rbase = g * 16;

    #pragma unroll 4
    for (int k = 0; k < K; ++k) {
        float wv = Ws[k * 64 + f];
        u64 wp = pack2(wv, wv);
        // 16 consecutive floats = 4x 16B shared loads = 8 packed pairs
        const ulonglong2* xr = (const ulonglong2*)&xst[k * 68 + rbase];
        ulonglong2 q0 = xr[0], q1 = xr[1], q2 = xr[2], q3 = xr[3];
        fma2(accp[0], q0.x, wp);
        fma2(accp[1], q0.y, wp);
        fma2(accp[2], q1.x, wp);
        fma2(accp[3], q1.y, wp);
        fma2(accp[4], q2.x, wp);
        fma2(accp[5], q2.y, wp);
        fma2(accp[6], q3.x, wp);
        fma2(accp[7], q3.y, wp);
    }

    #pragma unroll
    for (int i = 0; i < 8; ++i) {
        float lo, hi;
        unpack2(accp[i], lo, hi);
        int r0 = row0 + rbase + 2 * i;
        if (r0 < n)     xw[(size_t)r0 * 64 + f] = lo;
        if (r0 + 1 < n) xw[(size_t)(r0 + 1) * 64 + f] = hi;
    }
}

// ---------------------------------------------------------------------------
// Gather aggregation: half-warp (16 lanes) per node, lane owns one float4,
// packed f32x2 accumulation. rowptr holds row END; beg = end - deg.
template<bool TO_GH>
__global__ void k_aggr(const float* __restrict__ bias,
                       float4* __restrict__ outp, int n)
{
    float4* __restrict__ o = TO_GH ? g_h : outp;
    const ulonglong2* __restrict__ xwp = (const ulonglong2*)g_xw;

    int gtid = blockIdx.x * blockDim.x + threadIdx.x;
    int node = gtid >> 4;
    int lane = threadIdx.x & 15;
    if (node >= n) return;

    int end = g_rowptr[node];
    int deg = g_deg[node];
    int beg = end - deg;

    u64 aXY = 0ull, aZW = 0ull;
    int e = beg;
    for (; e + 4 <= end; e += 4) {
        int2 sw0 = g_csr[e];
        int2 sw1 = g_csr[e + 1];
        int2 sw2 = g_csr[e + 2];
        int2 sw3 = g_csr[e + 3];
        ulonglong2 v0 = xwp[(size_t)sw0.x * F4 + lane];
        ulonglong2 v1 = xwp[(size_t)sw1.x * F4 + lane];
        ulonglong2 v2 = xwp[(size_t)sw2.x * F4 + lane];
        ulonglong2 v3 = xwp[(size_t)sw3.x * F4 + lane];
        u64 w0 = pack2(__int_as_float(sw0.y), __int_as_float(sw0.y));
        u64 w1 = pack2(__int_as_float(sw1.y), __int_as_float(sw1.y));
        u64 w2 = pack2(__int_as_float(sw2.y), __int_as_float(sw2.y));
        u64 w3 = pack2(__int_as_float(sw3.y), __int_as_float(sw3.y));
        fma2(aXY, v0.x, w0); fma2(aZW, v0.y, w0);
        fma2(aXY, v1.x, w1); fma2(aZW, v1.y, w1);
        fma2(aXY, v2.x, w2); fma2(aZW, v2.y, w2);
        fma2(aXY, v3.x, w3); fma2(aZW, v3.y, w3);
    }
    for (; e < end; ++e) {
        int2 sw = g_csr[e];
        ulonglong2 v = xwp[(size_t)sw.x * F4 + lane];
        u64 w = pack2(__int_as_float(sw.y), __int_as_float(sw.y));
        fma2(aXY, v.x, w); fma2(aZW, v.y, w);
    }
    float di = g_dinv[node];
    float s2 = di * di;
    u64 sp = pack2(s2, s2);
    ulonglong2 self = xwp[(size_t)node * F4 + lane];
    fma2(aXY, self.x, sp);
    fma2(aZW, self.y, sp);

    float4 b4 = ((const float4*)bias)[lane];
    float4 acc;
    unpack2(aXY, acc.x, acc.y);
    unpack2(aZW, acc.z, acc.w);
    acc.x += b4.x; acc.y += b4.y; acc.z += b4.z; acc.w += b4.w;
    o[(size_t)node * F4 + lane] = acc;
}

// ---------------------------------------------------------------------------
extern "C" void kernel_launch(void* const* d_in, const int* in_sizes, int n_in,
                              void* d_out, int out_size)
{
    const float* x  = (const float*)d_in[0];
    const int*   ei = (const int*)d_in[1];
    const float* W1 = (const float*)d_in[2];
    const float* b1 = (const float*)d_in[3];
    const float* W2 = (const float*)d_in[4];
    const float* b2 = (const float*)d_in[5];
    float* out = (float*)d_out;

    const int IN = 128;
    int N = in_sizes[0] / IN;
    int E = in_sizes[1] / 2;
    const int* src = ei;
    const int* dst = ei + E;

    int nb256 = (N + 255) / 256;
    int gemm_blocks = (N + 63) / 64;
    int edge_blocks = 1184;
    int aggr_blocks = (N + 15) / 16;

    // --- graph preprocessing ---
    k_init<<<nb256, 256>>>(N);
    k_deg_count<<<edge_blocks, 256>>>(dst, E);
    k_scan_part<<<nb256, 256>>>(N);
    k_scan_mid<<<1, 512>>>(nb256);
    k_scan_apply<<<nb256, 256>>>(N);
    k_fill<<<edge_blocks, 256>>>(src, dst, E);

    // --- layer 1 ---
    k_gemm<128, false, false><<<gemm_blocks, 256>>>(x, W1, N);
    k_aggr<true><<<aggr_blocks, 256>>>(b1, nullptr, N);

    // --- layer 2 ---
    k_gemm<64, true, true><<<gemm_blocks, 256>>>(nullptr, W2, N);
    k_aggr<false><<<aggr_blocks, 256>>>(b2, (float4*)out, N);
}

// round 7
// speedup vs baseline: 1.4758x; 1.4758x over previous
#include <cuda_runtime.h>

// ---------------------------------------------------------------------------
// GCN_11682311045288: 2-layer GCN via per-launch CSR build + gather aggregation.
// Inputs: x [N,128] f32, edge_index [2,E] int32, W1[128,64], b1[64], W2[64,64], b2[64]
// Output: z [N,64] f32
// ---------------------------------------------------------------------------

#define MAXN 131072
#define MAXE 2097152
#define F 64
#define F4 (F / 4)

// Scratch (module-load allocated; allowed).
__device__ float4 g_xw[(size_t)MAXN * F4];
__device__ float4 g_h [(size_t)MAXN * F4];
__device__ float  g_dinv[MAXN];
__device__ int    g_deg [MAXN];
__device__ int    g_rowptr[MAXN];   // after k_fill: row end
__device__ int    g_part[512];
__device__ int2   g_csr[MAXE];

// L2-only float4 load (skip L1 for random gathers).
__device__ __forceinline__ float4 ldcg4(const float4* p) {
    float4 v;
    asm volatile("ld.global.cg.v4.f32 {%0, %1, %2, %3}, [%4];"
                 : "=f"(v.x), "=f"(v.y), "=f"(v.z), "=f"(v.w) : "l"(p));
    return v;
}

// ---------------------------------------------------------------------------
__global__ void k_init(int n) {
    int i = blockIdx.x * blockDim.x + threadIdx.x;
    if (i < n) g_deg[i] = 0;
}

__global__ void k_deg_count(const int* __restrict__ dst, int E) {
    int i = blockIdx.x * blockDim.x + threadIdx.x;
    int stride = gridDim.x * blockDim.x;
    int E4 = E >> 2;
    const int4* dst4 = (const int4*)dst;
    for (int j = i; j < E4; j += stride) {
        int4 d = dst4[j];
        atomicAdd(&g_deg[d.x], 1);
        atomicAdd(&g_deg[d.y], 1);
        atomicAdd(&g_deg[d.z], 1);
        atomicAdd(&g_deg[d.w], 1);
    }
    for (int j = (E4 << 2) + i; j < E; j += stride)
        atomicAdd(&g_deg[dst[j]], 1);
}

// --- 3-phase exclusive scan of g_deg -> g_rowptr ---------------------------
__global__ void k_scan_part(int n) {
    __shared__ int s[256];
    int t = threadIdx.x;
    int i = blockIdx.x * 256 + t;
    int v = (i < n) ? g_deg[i] : 0;
    s[t] = v;
    __syncthreads();
    #pragma unroll
    for (int off = 1; off < 256; off <<= 1) {
        int u = (t >= off) ? s[t - off] : 0;
        __syncthreads();
        s[t] += u;
        __syncthreads();
    }
    if (i < n) g_rowptr[i] = s[t] - v;
    if (t == 255) g_part[blockIdx.x] = s[255];
}

__global__ void k_scan_mid(int nb) {
    __shared__ int s[512];
    int t = threadIdx.x;
    int v = (t < nb) ? g_part[t] : 0;
    s[t] = v;
    __syncthreads();
    #pragma unroll
    for (int off = 1; off < 512; off <<= 1) {
        int u = (t >= off) ? s[t - off] : 0;
        __syncthreads();
        s[t] += u;
        __syncthreads();
    }
    if (t < nb) g_part[t] = s[t] - v;
}

__global__ void k_scan_apply(int n) {
    int i = blockIdx.x * 256 + threadIdx.x;
    if (i < n) {
        g_rowptr[i] += g_part[blockIdx.x];
        g_dinv[i] = rsqrtf((float)(g_deg[i] + 1));
    }
}

// Bumps g_rowptr[d]; after this kernel g_rowptr[i] = row end.
__global__ void k_fill(const int* __restrict__ src,
                       const int* __restrict__ dst, int E) {
    int i = blockIdx.x * blockDim.x + threadIdx.x;
    int stride = gridDim.x * blockDim.x;
    int E4 = E >> 2;
    const int4* src4 = (const int4*)src;
    const int4* dst4 = (const int4*)dst;
    for (int j = i; j < E4; j += stride) {
        int4 s = src4[j];
        int4 d = dst4[j];
        int p0 = atomicAdd(&g_rowptr[d.x], 1);
        g_csr[p0] = make_int2(s.x, __float_as_int(g_dinv[s.x] * g_dinv[d.x]));
        int p1 = atomicAdd(&g_rowptr[d.y], 1);
        g_csr[p1] = make_int2(s.y, __float_as_int(g_dinv[s.y] * g_dinv[d.y]));
        int p2 = atomicAdd(&g_rowptr[d.z], 1);
        g_csr[p2] = make_int2(s.z, __float_as_int(g_dinv[s.z] * g_dinv[d.z]));
        int p3 = atomicAdd(&g_rowptr[d.w], 1);
        g_csr[p3] = make_int2(s.w, __float_as_int(g_dinv[s.w] * g_dinv[d.w]));
    }
    for (int j = (E4 << 2) + i; j < E; j += stride) {
        int s = src[j], d = dst[j];
        int p = atomicAdd(&g_rowptr[d], 1);
        g_csr[p] = make_int2(s, __float_as_int(g_dinv[s] * g_dinv[d]));
    }
}

// ---------------------------------------------------------------------------
// Register-tiled GEMM: C[64x64] per block, 256 threads, 16 outputs/thread.
template<int K, bool RELU, bool READ_GH>
__global__ void k_gemm(const float* __restrict__ Xp,
                       const float* __restrict__ W,
                       int n)
{
    __shared__ float Ws[K * 64];
    __shared__ float xst[K * 68];

    const float* __restrict__ X = READ_GH ? (const float*)g_h : Xp;
    float* __restrict__ xw = (float*)g_xw;

    int tid = threadIdx.x;
    int f = tid & 63;
    int g = tid >> 6;
    int row0 = blockIdx.x * 64;

    {
        const float4* W4 = (const float4*)W;
        #pragma unroll
        for (int i = tid; i < K * 16; i += 256)
            ((float4*)Ws)[i] = W4[i];
    }
    {
        const int KQ = K / 4;
        #pragma unroll
        for (int i = tid; i < 64 * KQ; i += 256) {
            int r = i / KQ;
            int k4 = (i - r * KQ) * 4;
            int rr = row0 + r;
            float4 v = make_float4(0.f, 0.f, 0.f, 0.f);
            if (rr < n)
                v = ((const float4*)X)[((size_t)rr * K + k4) >> 2];
            if (RELU) {
                v.x = fmaxf(v.x, 0.f); v.y = fmaxf(v.y, 0.f);
                v.z = fmaxf(v.z, 0.f); v.w = fmaxf(v.w, 0.f);
            }
            xst[(k4 + 0) * 68 + r] = v.x;
            xst[(k4 + 1) * 68 + r] = v.y;
            xst[(k4 + 2) * 68 + r] = v.z;
            xst[(k4 + 3) * 68 + r] = v.w;
        }
    }
    __syncthreads();

    float acc[16];
    #pragma unroll
    for (int i = 0; i < 16; ++i) acc[i] = 0.f;
    const int rbase = g * 16;

    #pragma unroll 4
    for (int k = 0; k < K; ++k) {
        float wv = Ws[k * 64 + f];
        const float4* xr = (const float4*)&xst[k * 68 + rbase];
        float4 a = xr[0], b = xr[1], c = xr[2], d = xr[3];
        acc[0]  = fmaf(a.x, wv, acc[0]);
        acc[1]  = fmaf(a.y, wv, acc[1]);
        acc[2]  = fmaf(a.z, wv, acc[2]);
        acc[3]  = fmaf(a.w, wv, acc[3]);
        acc[4]  = fmaf(b.x, wv, acc[4]);
        acc[5]  = fmaf(b.y, wv, acc[5]);
        acc[6]  = fmaf(b.z, wv, acc[6]);
        acc[7]  = fmaf(b.w, wv, acc[7]);
        acc[8]  = fmaf(c.x, wv, acc[8]);
        acc[9]  = fmaf(c.y, wv, acc[9]);
        acc[10] = fmaf(c.z, wv, acc[10]);
        acc[11] = fmaf(c.w, wv, acc[11]);
        acc[12] = fmaf(d.x, wv, acc[12]);
        acc[13] = fmaf(d.y, wv, acc[13]);
        acc[14] = fmaf(d.z, wv, acc[14]);
        acc[15] = fmaf(d.w, wv, acc[15]);
    }

    #pragma unroll
    for (int i = 0; i < 16; ++i) {
        int r = row0 + rbase + i;
        if (r < n) xw[(size_t)r * 64 + f] = acc[i];
    }
}

// ---------------------------------------------------------------------------
// Gather aggregation: half-warp (16 lanes) per node, lane owns one float4.
// xw gathers via ld.global.cg (L2-only); unroll x8 for MLP.
template<bool TO_GH>
__global__ void k_aggr(const float* __restrict__ bias,
                       float4* __restrict__ outp, int n)
{
    float4* __restrict__ o = TO_GH ? g_h : outp;
    const float4* __restrict__ xw = g_xw;

    int gtid = blockIdx.x * blockDim.x + threadIdx.x;
    int node = gtid >> 4;
    int lane = threadIdx.x & 15;
    if (node >= n) return;

    int end = g_rowptr[node];
    int deg = g_deg[node];
    int beg = end - deg;

    float4 acc = make_float4(0.f, 0.f, 0.f, 0.f);
    int e = beg;
    for (; e + 8 <= end; e += 8) {
        int2 sw0 = g_csr[e];
        int2 sw1 = g_csr[e + 1];
        int2 sw2 = g_csr[e + 2];
        int2 sw3 = g_csr[e + 3];
        int2 sw4 = g_csr[e + 4];
        int2 sw5 = g_csr[e + 5];
        int2 sw6 = g_csr[e + 6];
        int2 sw7 = g_csr[e + 7];
        float4 v0 = ldcg4(xw + (size_t)sw0.x * F4 + lane);
        float4 v1 = ldcg4(xw + (size_t)sw1.x * F4 + lane);
        float4 v2 = ldcg4(xw + (size_t)sw2.x * F4 + lane);
        float4 v3 = ldcg4(xw + (size_t)sw3.x * F4 + lane);
        float4 v4 = ldcg4(xw + (size_t)sw4.x * F4 + lane);
        float4 v5 = ldcg4(xw + (size_t)sw5.x * F4 + lane);
        float4 v6 = ldcg4(xw + (size_t)sw6.x * F4 + lane);
        float4 v7 = ldcg4(xw + (size_t)sw7.x * F4 + lane);
        float w0 = __int_as_float(sw0.y);
        float w1 = __int_as_float(sw1.y);
        float w2 = __int_as_float(sw2.y);
        float w3 = __int_as_float(sw3.y);
        float w4 = __int_as_float(sw4.y);
        float w5 = __int_as_float(sw5.y);
        float w6 = __int_as_float(sw6.y);
        float w7 = __int_as_float(sw7.y);
        acc.x = fmaf(w0, v0.x, acc.x); acc.y = fmaf(w0, v0.y, acc.y);
        acc.z = fmaf(w0, v0.z, acc.z); acc.w = fmaf(w0, v0.w, acc.w);
        acc.x = fmaf(w1, v1.x, acc.x); acc.y = fmaf(w1, v1.y, acc.y);
        acc.z = fmaf(w1, v1.z, acc.z); acc.w = fmaf(w1, v1.w, acc.w);
        acc.x = fmaf(w2, v2.x, acc.x); acc.y = fmaf(w2, v2.y, acc.y);
        acc.z = fmaf(w2, v2.z, acc.z); acc.w = fmaf(w2, v2.w, acc.w);
        acc.x = fmaf(w3, v3.x, acc.x); acc.y = fmaf(w3, v3.y, acc.y);
        acc.z = fmaf(w3, v3.z, acc.z); acc.w = fmaf(w3, v3.w, acc.w);
        acc.x = fmaf(w4, v4.x, acc.x); acc.y = fmaf(w4, v4.y, acc.y);
        acc.z = fmaf(w4, v4.z, acc.z); acc.w = fmaf(w4, v4.w, acc.w);
        acc.x = fmaf(w5, v5.x, acc.x); acc.y = fmaf(w5, v5.y, acc.y);
        acc.z = fmaf(w5, v5.z, acc.z); acc.w = fmaf(w5, v5.w, acc.w);
        acc.x = fmaf(w6, v6.x, acc.x); acc.y = fmaf(w6, v6.y, acc.y);
        acc.z = fmaf(w6, v6.z, acc.z); acc.w = fmaf(w6, v6.w, acc.w);
        acc.x = fmaf(w7, v7.x, acc.x); acc.y = fmaf(w7, v7.y, acc.y);
        acc.z = fmaf(w7, v7.z, acc.z); acc.w = fmaf(w7, v7.w, acc.w);
    }
    for (; e < end; ++e) {
        int2 sw = g_csr[e];
        float w = __int_as_float(sw.y);
        float4 v = ldcg4(xw + (size_t)sw.x * F4 + lane);
        acc.x = fmaf(w, v.x, acc.x); acc.y = fmaf(w, v.y, acc.y);
        acc.z = fmaf(w, v.z, acc.z); acc.w = fmaf(w, v.w, acc.w);
    }
    float di = g_dinv[node];
    float sw2 = di * di;
    float4 self = xw[(size_t)node * F4 + lane];
    float4 b4 = ((const float4*)bias)[lane];
    acc.x = fmaf(sw2, self.x, acc.x) + b4.x;
    acc.y = fmaf(sw2, self.y, acc.y) + b4.y;
    acc.z = fmaf(sw2, self.z, acc.z) + b4.z;
    acc.w = fmaf(sw2, self.w, acc.w) + b4.w;
    o[(size_t)node * F4 + lane] = acc;
}

// ---------------------------------------------------------------------------
extern "C" void kernel_launch(void* const* d_in, const int* in_sizes, int n_in,
                              void* d_out, int out_size)
{
    const float* x  = (const float*)d_in[0];
    const int*   ei = (const int*)d_in[1];
    const float* W1 = (const float*)d_in[2];
    const float* b1 = (const float*)d_in[3];
    const float* W2 = (const float*)d_in[4];
    const float* b2 = (const float*)d_in[5];
    float* out = (float*)d_out;

    const int IN = 128;
    int N = in_sizes[0] / IN;
    int E = in_sizes[1] / 2;
    const int* src = ei;
    const int* dst = ei + E;

    int nb256 = (N + 255) / 256;
    int gemm_blocks = (N + 63) / 64;
    int edge_blocks = 1184;
    int aggr_blocks = (N + 15) / 16;

    // --- graph preprocessing ---
    k_init<<<nb256, 256>>>(N);
    k_deg_count<<<edge_blocks, 256>>>(dst, E);
    k_scan_part<<<nb256, 256>>>(N);
    k_scan_mid<<<1, 512>>>(nb256);
    k_scan_apply<<<nb256, 256>>>(N);
    k_fill<<<edge_blocks, 256>>>(src, dst, E);

    // --- layer 1 ---
    k_gemm<128, false, false><<<gemm_blocks, 256>>>(x, W1, N);
    k_aggr<true><<<aggr_blocks, 256>>>(b1, nullptr, N);

    // --- layer 2 ---
    k_gemm<64, true, true><<<gemm_blocks, 256>>>(nullptr, W2, N);
    k_aggr<false><<<aggr_blocks, 256>>>(b2, (float4*)out, N);
}

// round 10
// speedup vs baseline: 1.5355x; 1.0405x over previous
#include <cuda_runtime.h>
#include <cuda_fp16.h>

// ---------------------------------------------------------------------------
// GCN_11682311045288: 2-layer GCN via per-launch CSR build + gather aggregation.
// Edge messages gathered from an fp16 XW table (halves L2 gather traffic);
// self-loop + bias contribution written in fp32 by the GEMM.
// Inputs: x [N,128] f32, edge_index [2,E] int32, W1[128,64], b1[64], W2[64,64], b2[64]
// Output: z [N,64] f32
// ---------------------------------------------------------------------------

#define MAXN 131072
#define MAXE 2097152
#define F 64
#define F4 (F / 4)    // float4 groups per fp32 row: 16
#define FH16 16       // uint2 (4 halves) groups per fp16 row: 64/4 = 16

// Scratch (module-load allocated; allowed).
__device__ uint2  g_xwh[(size_t)MAXN * FH16]; // fp16 XW table, 128B per row
__device__ float4 g_h [(size_t)MAXN * F4];    // layer-1 result / layer-2 input
__device__ float  g_dinv[MAXN];
__device__ int    g_deg [MAXN];
__device__ int    g_rowptr[MAXN];             // after k_fill: row end
__device__ int    g_part[512];
__device__ int2   g_csr[MAXE];

__device__ __forceinline__ float2 h2f(unsigned u) {
    __half2 h = *reinterpret_cast<__half2*>(&u);
    return __half22float2(h);
}

// ---------------------------------------------------------------------------
__global__ void k_init(int n) {
    int i = blockIdx.x * blockDim.x + threadIdx.x;
    if (i < n) g_deg[i] = 0;
}

__global__ void k_deg_count(const int* __restrict__ dst, int E) {
    int i = blockIdx.x * blockDim.x + threadIdx.x;
    int stride = gridDim.x * blockDim.x;
    int E4 = E >> 2;
    const int4* dst4 = (const int4*)dst;
    for (int j = i; j < E4; j += stride) {
        int4 d = dst4[j];
        atomicAdd(&g_deg[d.x], 1);
        atomicAdd(&g_deg[d.y], 1);
        atomicAdd(&g_deg[d.z], 1);
        atomicAdd(&g_deg[d.w], 1);
    }
    for (int j = (E4 << 2) + i; j < E; j += stride)
        atomicAdd(&g_deg[dst[j]], 1);
}

// --- 3-phase exclusive scan of g_deg -> g_rowptr ---------------------------
__global__ void k_scan_part(int n) {
    __shared__ int s[256];
    int t = threadIdx.x;
    int i = blockIdx.x * 256 + t;
    int v = (i < n) ? g_deg[i] : 0;
    s[t] = v;
    __syncthreads();
    #pragma unroll
    for (int off = 1; off < 256; off <<= 1) {
        int u = (t >= off) ? s[t - off] : 0;
        __syncthreads();
        s[t] += u;
        __syncthreads();
    }
    if (i < n) g_rowptr[i] = s[t] - v;
    if (t == 255) g_part[blockIdx.x] = s[255];
}

__global__ void k_scan_mid(int nb) {
    __shared__ int s[512];
    int t = threadIdx.x;
    int v = (t < nb) ? g_part[t] : 0;
    s[t] = v;
    __syncthreads();
    #pragma unroll
    for (int off = 1; off < 512; off <<= 1) {
        int u = (t >= off) ? s[t - off] : 0;
        __syncthreads();
        s[t] += u;
        __syncthreads();
    }
    if (t < nb) g_part[t] = s[t] - v;
}

__global__ void k_scan_apply(int n) {
    int i = blockIdx.x * 256 + threadIdx.x;
    if (i < n) {
        g_rowptr[i] += g_part[blockIdx.x];
        g_dinv[i] = rsqrtf((float)(g_deg[i] + 1));
    }
}

// Bumps g_rowptr[d]; after this kernel g_rowptr[i] = row end.
__global__ void k_fill(const int* __restrict__ src,
                       const int* __restrict__ dst, int E) {
    int i = blockIdx.x * blockDim.x + threadIdx.x;
    int stride = gridDim.x * blockDim.x;
    int E4 = E >> 2;
    const int4* src4 = (const int4*)src;
    const int4* dst4 = (const int4*)dst;
    for (int j = i; j < E4; j += stride) {
        int4 s = src4[j];
        int4 d = dst4[j];
        int p0 = atomicAdd(&g_rowptr[d.x], 1);
        g_csr[p0] = make_int2(s.x, __float_as_int(g_dinv[s.x] * g_dinv[d.x]));
        int p1 = atomicAdd(&g_rowptr[d.y], 1);
        g_csr[p1] = make_int2(s.y, __float_as_int(g_dinv[s.y] * g_dinv[d.y]));
        int p2 = atomicAdd(&g_rowptr[d.z], 1);
        g_csr[p2] = make_int2(s.z, __float_as_int(g_dinv[s.z] * g_dinv[d.z]));
        int p3 = atomicAdd(&g_rowptr[d.w], 1);
        g_csr[p3] = make_int2(s.w, __float_as_int(g_dinv[s.w] * g_dinv[d.w]));
    }
    for (int j = (E4 << 2) + i; j < E; j += stride) {
        int s = src[j], d = dst[j];
        int p = atomicAdd(&g_rowptr[d], 1);
        g_csr[p] = make_int2(s, __float_as_int(g_dinv[s] * g_dinv[d]));
    }
}

// ---------------------------------------------------------------------------
// Register-tiled GEMM: C[64x64] per block, 256 threads, 16 outputs/thread.
// Emits: fp16 table row (for edge gathers) + fp32 init = dinv^2*acc + bias.
// READ_GH: input rows from g_h (with optional RELU); else from Xp.
// STORE_GH: init rows go to g_h; else to outp.
template<int K, bool RELU, bool READ_GH, bool STORE_GH>
__global__ void k_gemm(const float* __restrict__ Xp,
                       const float* __restrict__ W,
                       const float* __restrict__ bias,
                       float* __restrict__ outp,
                       int n)
{
    __shared__ float Ws[K * 64];
    __shared__ float xst[K * 68];

    const float* __restrict__ X = READ_GH ? (const float*)g_h : Xp;
    float* __restrict__ oinit = STORE_GH ? (float*)g_h : outp;
    __half* __restrict__ xwh = (__half*)g_xwh;

    int tid = threadIdx.x;
    int f = tid & 63;
    int g = tid >> 6;
    int row0 = blockIdx.x * 64;

    {
        const float4* W4 = (const float4*)W;
        #pragma unroll
        for (int i = tid; i < K * 16; i += 256)
            ((float4*)Ws)[i] = W4[i];
    }
    {
        const int KQ = K / 4;
        #pragma unroll
        for (int i = tid; i < 64 * KQ; i += 256) {
            int r = i / KQ;
            int k4 = (i - r * KQ) * 4;
            int rr = row0 + r;
            float4 v = make_float4(0.f, 0.f, 0.f, 0.f);
            if (rr < n)
                v = ((const float4*)X)[((size_t)rr * K + k4) >> 2];
            if (RELU) {
                v.x = fmaxf(v.x, 0.f); v.y = fmaxf(v.y, 0.f);
                v.z = fmaxf(v.z, 0.f); v.w = fmaxf(v.w, 0.f);
            }
            xst[(k4 + 0) * 68 + r] = v.x;
            xst[(k4 + 1) * 68 + r] = v.y;
            xst[(k4 + 2) * 68 + r] = v.z;
            xst[(k4 + 3) * 68 + r] = v.w;
        }
    }
    __syncthreads();

    float acc[16];
    #pragma unroll
    for (int i = 0; i < 16; ++i) acc[i] = 0.f;
    const int rbase = g * 16;

    #pragma unroll 4
    for (int k = 0; k < K; ++k) {
        float wv = Ws[k * 64 + f];
        const float4* xr = (const float4*)&xst[k * 68 + rbase];
        float4 a = xr[0], b = xr[1], c = xr[2], d = xr[3];
        acc[0]  = fmaf(a.x, wv, acc[0]);
        acc[1]  = fmaf(a.y, wv, acc[1]);
        acc[2]  = fmaf(a.z, wv, acc[2]);
        acc[3]  = fmaf(a.w, wv, acc[3]);
        acc[4]  = fmaf(b.x, wv, acc[4]);
        acc[5]  = fmaf(b.y, wv, acc[5]);
        acc[6]  = fmaf(b.z, wv, acc[6]);
        acc[7]  = fmaf(b.w, wv, acc[7]);
        acc[8]  = fmaf(c.x, wv, acc[8]);
        acc[9]  = fmaf(c.y, wv, acc[9]);
        acc[10] = fmaf(c.z, wv, acc[10]);
        acc[11] = fmaf(c.w, wv, acc[11]);
        acc[12] = fmaf(d.x, wv, acc[12]);
        acc[13] = fmaf(d.y, wv, acc[13]);
        acc[14] = fmaf(d.z, wv, acc[14]);
        acc[15] = fmaf(d.w, wv, acc[15]);
    }

    float bf = bias[f];
    #pragma unroll
    for (int i = 0; i < 16; ++i) {
        int r = row0 + rbase + i;
        if (r < n) {
            xwh[(size_t)r * 64 + f] = __float2half_rn(acc[i]);
            float di = g_dinv[r];
            oinit[(size_t)r * 64 + f] = fmaf(di * di, acc[i], bf);
        }
    }
}

// ---------------------------------------------------------------------------
// Gather aggregation: half-warp (16 lanes) per node, lane owns 4 features.
// Gathers fp16 rows (uint2 = 4 halves per lane, L2-only via __ldcg),
// accumulates fp32, adds the GEMM-written fp32 init row, stores fp32.
template<bool TO_GH>
__global__ void k_aggr(float4* __restrict__ outp, int n)
{
    float4* __restrict__ o = TO_GH ? g_h : outp;
    const uint2* __restrict__ xwh = g_xwh;

    int gtid = blockIdx.x * blockDim.x + threadIdx.x;
    int node = gtid >> 4;
    int lane = threadIdx.x & 15;
    if (node >= n) return;

    int end = g_rowptr[node];
    int deg = g_deg[node];
    int beg = end - deg;

    float4 acc = make_float4(0.f, 0.f, 0.f, 0.f);
    int e = beg;
    for (; e + 8 <= end; e += 8) {
        int2 sw0 = g_csr[e];
        int2 sw1 = g_csr[e + 1];
        int2 sw2 = g_csr[e + 2];
        int2 sw3 = g_csr[e + 3];
        int2 sw4 = g_csr[e + 4];
        int2 sw5 = g_csr[e + 5];
        int2 sw6 = g_csr[e + 6];
        int2 sw7 = g_csr[e + 7];
        uint2 q0 = __ldcg(xwh + (size_t)sw0.x * FH16 + lane);
        uint2 q1 = __ldcg(xwh + (size_t)sw1.x * FH16 + lane);
        uint2 q2 = __ldcg(xwh + (size_t)sw2.x * FH16 + lane);
        uint2 q3 = __ldcg(xwh + (size_t)sw3.x * FH16 + lane);
        uint2 q4 = __ldcg(xwh + (size_t)sw4.x * FH16 + lane);
        uint2 q5 = __ldcg(xwh + (size_t)sw5.x * FH16 + lane);
        uint2 q6 = __ldcg(xwh + (size_t)sw6.x * FH16 + lane);
        uint2 q7 = __ldcg(xwh + (size_t)sw7.x * FH16 + lane);
        #define ACC_EDGE(q, sw) do {                                         \
            float w_ = __int_as_float((sw).y);                               \
            float2 a_ = h2f((q).x);                                          \
            float2 b_ = h2f((q).y);                                          \
            acc.x = fmaf(w_, a_.x, acc.x); acc.y = fmaf(w_, a_.y, acc.y);    \
            acc.z = fmaf(w_, b_.x, acc.z); acc.w = fmaf(w_, b_.y, acc.w);    \
        } while (0)
        ACC_EDGE(q0, sw0); ACC_EDGE(q1, sw1); ACC_EDGE(q2, sw2); ACC_EDGE(q3, sw3);
        ACC_EDGE(q4, sw4); ACC_EDGE(q5, sw5); ACC_EDGE(q6, sw6); ACC_EDGE(q7, sw7);
    }
    for (; e < end; ++e) {
        int2 sw = g_csr[e];
        uint2 q = __ldcg(xwh + (size_t)sw.x * FH16 + lane);
        ACC_EDGE(q, sw);
    }
    #undef ACC_EDGE

    float4* p = o + (size_t)node * F4 + lane;
    float4 init = *p;
    init.x += acc.x; init.y += acc.y; init.z += acc.z; init.w += acc.w;
    *p = init;
}

// ---------------------------------------------------------------------------
extern "C" void kernel_launch(void* const* d_in, const int* in_sizes, int n_in,
                              void* d_out, int out_size)
{
    const float* x  = (const float*)d_in[0];
    const int*   ei = (const int*)d_in[1];
    const float* W1 = (const float*)d_in[2];
    const float* b1 = (const float*)d_in[3];
    const float* W2 = (const float*)d_in[4];
    const float* b2 = (const float*)d_in[5];
    float* out = (float*)d_out;

    const int IN = 128;
    int N = in_sizes[0] / IN;
    int E = in_sizes[1] / 2;
    const int* src = ei;
    const int* dst = ei + E;

    int nb256 = (N + 255) / 256;
    int gemm_blocks = (N + 63) / 64;
    int edge_blocks = 1184;
    int aggr_blocks = (N + 15) / 16;

    // --- graph preprocessing ---
    k_init<<<nb256, 256>>>(N);
    k_deg_count<<<edge_blocks, 256>>>(dst, E);
    k_scan_part<<<nb256, 256>>>(N);
    k_scan_mid<<<1, 512>>>(nb256);
    k_scan_apply<<<nb256, 256>>>(N);
    k_fill<<<edge_blocks, 256>>>(src, dst, E);

    // --- layer 1: init rows -> g_h, aggregate into g_h ---
    k_gemm<128, false, false, true><<<gemm_blocks, 256>>>(x, W1, b1, nullptr, N);
    k_aggr<true><<<aggr_blocks, 256>>>(nullptr, N);

    // --- layer 2: init rows -> out, aggregate into out ---
    k_gemm<64, true, true, false><<<gemm_blocks, 256>>>(nullptr, W2, b2, out, N);
    k_aggr<false><<<aggr_blocks, 256>>>((float4*)out, N);
}